// round 2
// baseline (speedup 1.0000x reference)
#include <cuda_runtime.h>
#include <math.h>

#define N_   32
#define C_   512
#define HW_  4096          // 64*64
#define D_   4
#define BLK_ 128           // C_/D_
#define HID_ 32            // C_/16

// ---- scratch (no allocations allowed) ----
__device__ float g_avgp[N_ * C_];
__device__ float g_maxp[N_ * C_];
__device__ int   g_idx [N_ * C_];   // N x (D*BLK) selected channel ids, in output order

// ---------------------------------------------------------------------------
// K1: per-(n,c) avg + max pooling over HW_ elements. One block per row.
// ---------------------------------------------------------------------------
__global__ __launch_bounds__(256) void pool_kernel(const float* __restrict__ x) {
    const int row = blockIdx.x;                      // n*C + c
    const float4* xr = reinterpret_cast<const float4*>(x + (size_t)row * HW_);

    float s = 0.0f;
    float m = -INFINITY;
    #pragma unroll 4
    for (int i = threadIdx.x; i < HW_ / 4; i += 256) {
        float4 v = xr[i];
        s += (v.x + v.y) + (v.z + v.w);
        m = fmaxf(m, fmaxf(fmaxf(v.x, v.y), fmaxf(v.z, v.w)));
    }
    // warp reduce
    #pragma unroll
    for (int off = 16; off > 0; off >>= 1) {
        s += __shfl_xor_sync(0xffffffffu, s, off);
        m = fmaxf(m, __shfl_xor_sync(0xffffffffu, m, off));
    }
    __shared__ float ss[8], sm[8];
    const int wid = threadIdx.x >> 5;
    const int lid = threadIdx.x & 31;
    if (lid == 0) { ss[wid] = s; sm[wid] = m; }
    __syncthreads();
    if (threadIdx.x == 0) {
        float ts = ss[0], tm = sm[0];
        #pragma unroll
        for (int w = 1; w < 8; w++) { ts += ss[w]; tm = fmaxf(tm, sm[w]); }
        g_avgp[row] = ts * (1.0f / HW_);
        g_maxp[row] = tm;
    }
}

// ---------------------------------------------------------------------------
// K2: MLP + sigmoid + per-(n,d) top-128 rank selection. One block per sample.
//   attn[n, c*D + d] ; per scale d: rank channel c among 512 by
//   (value desc, index asc) — exactly lax.top_k order.
// ---------------------------------------------------------------------------
__global__ __launch_bounds__(512) void mlp_topk_kernel(
    const float* __restrict__ W1, const float* __restrict__ b1,
    const float* __restrict__ W2, const float* __restrict__ b2) {
    const int n   = blockIdx.x;
    const int tid = threadIdx.x;

    __shared__ float avg_s[C_];
    __shared__ float max_s[C_];
    __shared__ float hs[HID_];       // relu(avg@W1+b1) + relu(max@W1+b1)
    __shared__ float attn_s[C_ * D_];

    avg_s[tid] = g_avgp[n * C_ + tid];
    max_s[tid] = g_maxp[n * C_ + tid];
    __syncthreads();

    // Layer 1: 32 outputs, 16 threads per output (groups of 16 lanes).
    {
        const int j = tid >> 4;      // 0..31
        const int k = tid & 15;
        float sa = 0.0f, smx = 0.0f;
        for (int c = k; c < C_; c += 16) {
            float w = W1[c * HID_ + j];
            sa  = fmaf(avg_s[c], w, sa);
            smx = fmaf(max_s[c], w, smx);
        }
        #pragma unroll
        for (int off = 8; off > 0; off >>= 1) {
            sa  += __shfl_xor_sync(0xffffffffu, sa,  off);
            smx += __shfl_xor_sync(0xffffffffu, smx, off);
        }
        if (k == 0) {
            float bb = b1[j];
            hs[j] = fmaxf(sa + bb, 0.0f) + fmaxf(smx + bb, 0.0f);
        }
    }
    __syncthreads();

    // Layer 2 + sigmoid: 2048 outputs, 4 per thread.
    for (int o = tid; o < C_ * D_; o += 512) {
        float acc = 2.0f * b2[o];
        #pragma unroll
        for (int k = 0; k < HID_; k++)
            acc = fmaf(hs[k], W2[k * (C_ * D_) + o], acc);
        attn_s[o] = 1.0f / (1.0f + expf(-acc));
    }
    __syncthreads();

    // Rank selection per scale d: thread tid handles channel c=tid.
    const int c = tid;
    for (int d = 0; d < D_; d++) {
        const float v = attn_s[c * D_ + d];
        int rank = 0;
        #pragma unroll 8
        for (int k = 0; k < C_; k++) {
            float u = attn_s[k * D_ + d];
            rank += (u > v) || (u == v && k < c);
        }
        if (rank < BLK_)
            g_idx[n * C_ + d * BLK_ + rank] = c;
    }
}

// ---------------------------------------------------------------------------
// K3: gather — copy the selected channel planes. One block per output row.
// ---------------------------------------------------------------------------
__global__ __launch_bounds__(256) void gather_kernel(
    const float* __restrict__ x, float* __restrict__ out) {
    const int row = blockIdx.x;              // n*512 + j
    const int n   = row >> 9;
    const int c   = g_idx[row];
    const float4* src = reinterpret_cast<const float4*>(
        x + ((size_t)n * C_ + c) * HW_);
    float4* dst = reinterpret_cast<float4*>(out + (size_t)row * HW_);
    #pragma unroll 4
    for (int i = threadIdx.x; i < HW_ / 4; i += 256)
        dst[i] = src[i];
}

extern "C" void kernel_launch(void* const* d_in, const int* in_sizes, int n_in,
                              void* d_out, int out_size) {
    const float* x  = (const float*)d_in[0];
    const float* W1 = (const float*)d_in[1];
    const float* b1 = (const float*)d_in[2];
    const float* W2 = (const float*)d_in[3];
    const float* b2 = (const float*)d_in[4];
    float* out = (float*)d_out;

    pool_kernel<<<N_ * C_, 256>>>(x);
    mlp_topk_kernel<<<N_, 512>>>(W1, b1, W2, b2);
    gather_kernel<<<N_ * C_, 256>>>(x, out);
}

// round 5
// speedup vs baseline: 1.2808x; 1.2808x over previous
#include <cuda_runtime.h>
#include <math.h>
#include <stdint.h>

#define N_   32
#define C_   512
#define HW_  4096          // 64*64
#define D_   4
#define BLK_ 128           // C_/D_
#define HID_ 32            // C_/16

// ---- scratch (no allocations allowed) ----
__device__ float              g_avgp[N_ * C_];
__device__ float              g_maxp[N_ * C_];
__device__ unsigned long long g_keys[N_ * D_ * C_];  // sortable keys, [n][d][c]
__device__ int                g_idx [N_ * C_];       // selected channels, output order

// ---------------------------------------------------------------------------
// K1: per-(n,c) avg + max pooling over HW_ elements. One block per row.
// (83.5% DRAM peak — leave alone.)
// ---------------------------------------------------------------------------
__global__ __launch_bounds__(256) void pool_kernel(const float* __restrict__ x) {
    const int row = blockIdx.x;                      // n*C + c
    const float4* xr = reinterpret_cast<const float4*>(x + (size_t)row * HW_);

    float s = 0.0f;
    float m = -INFINITY;
    #pragma unroll 4
    for (int i = threadIdx.x; i < HW_ / 4; i += 256) {
        float4 v = xr[i];
        s += (v.x + v.y) + (v.z + v.w);
        m = fmaxf(m, fmaxf(fmaxf(v.x, v.y), fmaxf(v.z, v.w)));
    }
    #pragma unroll
    for (int off = 16; off > 0; off >>= 1) {
        s += __shfl_xor_sync(0xffffffffu, s, off);
        m = fmaxf(m, __shfl_xor_sync(0xffffffffu, m, off));
    }
    __shared__ float ss[8], sm[8];
    const int wid = threadIdx.x >> 5;
    const int lid = threadIdx.x & 31;
    if (lid == 0) { ss[wid] = s; sm[wid] = m; }
    __syncthreads();
    if (threadIdx.x == 0) {
        float ts = ss[0], tm = sm[0];
        #pragma unroll
        for (int w = 1; w < 8; w++) { ts += ss[w]; tm = fmaxf(tm, sm[w]); }
        g_avgp[row] = ts * (1.0f / HW_);
        g_maxp[row] = tm;
    }
}

// ---------------------------------------------------------------------------
// K2a: MLP + sigmoid -> sortable 64-bit keys. One block per sample.
//   key = (bits(sigmoid) << 16) | (65535 - c): since sigmoid > 0, float bits
//   are monotone; index tiebreak (lower c wins) embedded in low bits.
// ---------------------------------------------------------------------------
__global__ __launch_bounds__(512) void mlp_key_kernel(
    const float* __restrict__ W1, const float* __restrict__ b1,
    const float* __restrict__ W2, const float* __restrict__ b2) {
    const int n   = blockIdx.x;
    const int tid = threadIdx.x;

    __shared__ float avg_s[C_];
    __shared__ float max_s[C_];
    __shared__ float hs[HID_];       // relu(avg@W1+b1) + relu(max@W1+b1)

    avg_s[tid] = g_avgp[n * C_ + tid];
    max_s[tid] = g_maxp[n * C_ + tid];
    __syncthreads();

    // Layer 1: 32 outputs, 16 lanes per output.
    {
        const int j = tid >> 4;      // 0..31
        const int k = tid & 15;
        float sa = 0.0f, smx = 0.0f;
        for (int c = k; c < C_; c += 16) {
            float w = W1[c * HID_ + j];
            sa  = fmaf(avg_s[c], w, sa);
            smx = fmaf(max_s[c], w, smx);
        }
        #pragma unroll
        for (int off = 8; off > 0; off >>= 1) {
            sa  += __shfl_xor_sync(0xffffffffu, sa,  off);
            smx += __shfl_xor_sync(0xffffffffu, smx, off);
        }
        if (k == 0) {
            float bb = b1[j];
            hs[j] = fmaxf(sa + bb, 0.0f) + fmaxf(smx + bb, 0.0f);
        }
    }
    __syncthreads();

    // Layer 2 + sigmoid + key build: 2048 outputs, 4 per thread.
    for (int o = tid; o < C_ * D_; o += 512) {
        float acc = 2.0f * b2[o];
        #pragma unroll
        for (int k = 0; k < HID_; k++)
            acc = fmaf(hs[k], W2[k * (C_ * D_) + o], acc);
        float v = 1.0f / (1.0f + expf(-acc));
        const int c = o >> 2;
        const int d = o & 3;
        unsigned long long key =
            ((unsigned long long)__float_as_uint(v) << 16) |
            (unsigned long long)(65535 - c);
        g_keys[((size_t)n * D_ + d) * C_ + c] = key;
    }
}

// ---------------------------------------------------------------------------
// K2b: rank selection. One block per (n, d); thread c counts keys > its key.
//   rank < 128  ->  g_idx[n*C + d*128 + rank] = c
// ---------------------------------------------------------------------------
__global__ __launch_bounds__(512) void rank_kernel() {
    const int b   = blockIdx.x;      // n*D + d
    const int n   = b >> 2;
    const int d   = b & 3;
    const int c   = threadIdx.x;

    __shared__ unsigned long long keys[C_];
    keys[c] = g_keys[(size_t)b * C_ + c];
    __syncthreads();

    const unsigned long long myk = keys[c];
    int rank = 0;
    const ulonglong2* k2 = reinterpret_cast<const ulonglong2*>(keys);
    #pragma unroll 8
    for (int i = 0; i < C_ / 2; i++) {
        ulonglong2 u = k2[i];
        rank += (u.x > myk) + (u.y > myk);
    }
    if (rank < BLK_)
        g_idx[n * C_ + d * BLK_ + rank] = c;
}

// ---------------------------------------------------------------------------
// K3: gather — copy the selected channel planes. One block per output row.
// Streaming hints: neither stream has reuse.
// ---------------------------------------------------------------------------
__global__ __launch_bounds__(256) void gather_kernel(
    const float* __restrict__ x, float* __restrict__ out) {
    const int row = blockIdx.x;              // n*512 + j
    const int n   = row >> 9;
    const int c   = g_idx[row];
    const float4* src = reinterpret_cast<const float4*>(
        x + ((size_t)n * C_ + c) * HW_);
    float4* dst = reinterpret_cast<float4*>(out + (size_t)row * HW_);
    #pragma unroll 4
    for (int i = threadIdx.x; i < HW_ / 4; i += 256) {
        float4 v = __ldcs(src + i);
        __stcs(dst + i, v);
    }
}

extern "C" void kernel_launch(void* const* d_in, const int* in_sizes, int n_in,
                              void* d_out, int out_size) {
    const float* x  = (const float*)d_in[0];
    const float* W1 = (const float*)d_in[1];
    const float* b1 = (const float*)d_in[2];
    const float* W2 = (const float*)d_in[3];
    const float* b2 = (const float*)d_in[4];
    float* out = (float*)d_out;

    pool_kernel<<<N_ * C_, 256>>>(x);
    mlp_key_kernel<<<N_, 512>>>(W1, b1, W2, b2);
    rank_kernel<<<N_ * D_, 512>>>();
    gather_kernel<<<N_ * C_, 256>>>(x, out);
}